// round 8
// baseline (speedup 1.0000x reference)
#include <cuda_runtime.h>
#include <cuda.h>
#include <cuda_bf16.h>
#include <cstdint>

// ---------------------------------------------------------------------------
// Problem constants
// ---------------------------------------------------------------------------
#define TOKENS 8192
#define IN_F   4096
#define OUT_F  16384

#define TILE_M 128
#define TILE_N 256
#define GTHREADS 128
#define CLUSTER 2

// bf16 tcgen05 path: 64 bf16 per stage-row (128B = SW128 atom)
#define KC     64
#define NKI    (IN_F / KC)           // 64 K-iterations
#define NSTAGE 2

// Shared memory layout (tcgen05 path, dynamic)
#define SM_TMEMPTR 0
#define SM_FULL(s) (64 + (s) * 8)
#define SM_DONE(s) (96 + (s) * 8)
#define SM_FINAL   128
#define SM_TILES   1024
#define A_BYTES    (TILE_M * KC * 2)          // 16384
#define B_BYTES    (TILE_N * KC * 2)          // 32768
#define B_HALF     (B_BYTES / 2)              // 16384
#define STAGE_BYTES (A_BYTES + B_BYTES)       // 49152
#define SM_A(s) (SM_TILES + (s) * STAGE_BYTES)
#define SM_B(s) (SM_A(s) + A_BYTES)
#define SMEM_TOTAL (SM_TILES + NSTAGE * STAGE_BYTES)  // 99328 -> 2 CTAs/SM

// Arch-specific feature gate: tcgen05 legal only on sm_100a / sm_103a targets.
#if defined(__CUDA_ARCH_FEAT_SM103_ALL) || defined(__CUDA_ARCH_FEAT_SM100_ALL)
#define HAS_TCGEN05 1
#else
#define HAS_TCGEN05 0
#endif

// idesc for kind::f16: dtype=F32 (bit4), atype=BF16 (bit7), btype=BF16 (bit10),
// N/8 at bit17, M/16 at bit24. (Validated R5: passed, rel_err 5.7e-8.)
static constexpr uint32_t MMA_IDESC =
    (1u << 4) | (1u << 7) | (1u << 10) |
    ((TILE_N / 8u) << 17) | ((TILE_M / 16u) << 24);

// Scratch (device-global scratch is the sanctioned no-alloc path).
// tcgen05 path: bf16. Fallback path: reinterpreted as int8.
__device__ __nv_bfloat16 g_xb[(size_t)TOKENS * IN_F];   // 64 MB
__device__ __nv_bfloat16 g_wb[(size_t)OUT_F * IN_F];    // 128 MB

// ---------------------------------------------------------------------------
// Common PTX helpers
// ---------------------------------------------------------------------------
__device__ __forceinline__ uint32_t elect_one_pred() {
    uint32_t pred;
    asm volatile(
        "{\n\t.reg .pred p;\n\telect.sync _|p, 0xFFFFFFFF;\n\t"
        "selp.b32 %0, 1, 0, p;\n\t}" : "=r"(pred));
    return pred;
}

__device__ __forceinline__ uint32_t smem_u32(const void* p) {
    uint32_t a;
    asm("{ .reg .u64 t; cvta.to.shared.u64 t, %1; cvt.u32.u64 %0, t; }"
        : "=r"(a) : "l"(p));
    return a;
}

#define MBARRIER_INIT(addr, cnt) \
    asm volatile("mbarrier.init.shared.b64 [%0], %1;" :: "r"((uint32_t)(addr)), "r"((uint32_t)(cnt)) : "memory")

#define MBARRIER_EXPECT_TX(addr, tx) \
    asm volatile("mbarrier.arrive.expect_tx.shared.b64 _, [%0], %1;" :: "r"((uint32_t)(addr)), "r"((uint32_t)(tx)) : "memory")

#define MBARRIER_WAIT_PARITY(mbar_smem_addr, phase_parity) do { \
    uint32_t _mbar = (uint32_t)(mbar_smem_addr); \
    uint32_t _parity = (uint32_t)(phase_parity); \
    uint32_t _done_; \
    asm volatile( \
        "{\n\t.reg .pred p;\n\t" \
        "mbarrier.try_wait.parity.acquire.cta.shared::cta.b64 p, [%1], %2;\n\t" \
        "selp.b32 %0, 1, 0, p;\n\t}" \
        : "=r"(_done_) : "r"(_mbar), "r"(_parity) : "memory"); \
    if (!_done_) { \
        asm volatile( \
            "{\n\t.reg .pred P1;\n\t" \
            "WAIT_LOOP_%=:\n\t" \
            "mbarrier.try_wait.parity.acquire.cta.shared::cta.b64 P1, [%0], %1, 0x989680;\n\t" \
            "@P1 bra.uni WAIT_DONE_%=;\n\t" \
            "bra.uni WAIT_LOOP_%=;\n\t" \
            "WAIT_DONE_%=:\n\t}" \
            :: "r"(_mbar), "r"(_parity) : "memory"); \
    } \
} while (0)

#define CLUSTER_SYNC() do { \
    asm volatile("barrier.cluster.arrive.aligned;" ::: "memory"); \
    asm volatile("barrier.cluster.wait.aligned;"   ::: "memory"); \
} while (0)

// ---------------------------------------------------------------------------
// tcgen05 macros (only EXPANDED inside HAS_TCGEN05 regions)
// ---------------------------------------------------------------------------
#define TCGEN05_ALLOC(smem_result_addr, nCols) \
    asm volatile("tcgen05.alloc.cta_group::1.sync.aligned.shared::cta.b32 [%0], %1;" \
        :: "r"((uint32_t)(smem_result_addr)), "r"((uint32_t)(nCols)) : "memory")

#define TCGEN05_DEALLOC(tmem_addr, nCols) \
    asm volatile("tcgen05.dealloc.cta_group::1.sync.aligned.b32 %0, %1;" \
        :: "r"(tmem_addr), "r"((uint32_t)(nCols)))

#define TCGEN05_RELINQUISH() \
    asm volatile("tcgen05.relinquish_alloc_permit.cta_group::1.sync.aligned;")

#define TCGEN05_COMMIT(mbar_smem_addr) \
    asm volatile("tcgen05.commit.cta_group::1.mbarrier::arrive::one.shared::cluster.b64 [%0];" \
        :: "r"((uint32_t)(mbar_smem_addr)) : "memory")

// Multicast commit: arrive on the mbarrier at this SMEM offset in every CTA
// whose bit is set (done-barriers need BOTH CTAs' MMA completion before refill,
// because refills multicast into the peer's SMEM).
#define TCGEN05_COMMIT_MC(mbar_smem_addr, mask) \
    asm volatile("tcgen05.commit.cta_group::1.mbarrier::arrive::one.shared::cluster.multicast::cluster.b64 [%0], %1;" \
        :: "r"((uint32_t)(mbar_smem_addr)), "h"((uint16_t)(mask)) : "memory")

#define TCGEN05_WAIT_LD() \
    asm volatile("tcgen05.wait::ld.sync.aligned;" ::: "memory")

#define TCGEN05_FENCE_BEFORE() \
    asm volatile("tcgen05.fence::before_thread_sync;" ::: "memory")

#define TCGEN05_FENCE_AFTER() \
    asm volatile("tcgen05.fence::after_thread_sync;" ::: "memory")

#define TCGEN05_LD_32X32B_X32(r, tmem_addr) \
    asm volatile( \
        "tcgen05.ld.sync.aligned.32x32b.x32.b32 " \
        "{%0, %1, %2, %3, %4, %5, %6, %7, " \
        " %8, %9, %10, %11, %12, %13, %14, %15, " \
        " %16, %17, %18, %19, %20, %21, %22, %23, " \
        " %24, %25, %26, %27, %28, %29, %30, %31}, [%32];" \
        : "=r"((r)[0]),  "=r"((r)[1]),  "=r"((r)[2]),  "=r"((r)[3]), \
          "=r"((r)[4]),  "=r"((r)[5]),  "=r"((r)[6]),  "=r"((r)[7]), \
          "=r"((r)[8]),  "=r"((r)[9]),  "=r"((r)[10]), "=r"((r)[11]), \
          "=r"((r)[12]), "=r"((r)[13]), "=r"((r)[14]), "=r"((r)[15]), \
          "=r"((r)[16]), "=r"((r)[17]), "=r"((r)[18]), "=r"((r)[19]), \
          "=r"((r)[20]), "=r"((r)[21]), "=r"((r)[22]), "=r"((r)[23]), \
          "=r"((r)[24]), "=r"((r)[25]), "=r"((r)[26]), "=r"((r)[27]), \
          "=r"((r)[28]), "=r"((r)[29]), "=r"((r)[30]), "=r"((r)[31]) \
        : "r"(tmem_addr))

// SW128 K-major descriptor (LBO=1, SBO=64, version=1, layout=SW128)
static constexpr unsigned long long SMEM_DESC_BASE_SW128 =
    (2ull << 61) | (1ull << 46) | (64ull << 32) | (1ull << 16);

__device__ __forceinline__ uint64_t make_desc(uint32_t smem_addr) {
    return SMEM_DESC_BASE_SW128 | ((uint64_t)(smem_addr >> 4) & 0x3FFFull);
}

#if HAS_TCGEN05
__device__ __forceinline__ void mma_bf16_ss(uint32_t d_tmem, uint64_t a_desc,
                                            uint64_t b_desc, uint32_t idesc,
                                            uint32_t enable_d) {
    asm volatile(
        "{\n\t.reg .pred p;\n\t"
        "setp.ne.u32 p, %5, 0;\n\t"
        "tcgen05.mma.cta_group::1.kind::f16 [%0], %1, %2, %3, {%4, %4, %4, %4}, p;\n\t}"
        :: "r"(d_tmem), "l"(a_desc), "l"(b_desc), "r"(idesc), "r"(0u), "r"(enable_d)
        : "memory");
}

__device__ __forceinline__ void tma_ld2(uint32_t smem_addr, const CUtensorMap* tmap,
                                        int cx, int cy, uint32_t mbar) {
    asm volatile(
        "cp.async.bulk.tensor.2d.shared::cta.global.tile.mbarrier::complete_tx::bytes "
        "[%0], [%1, {%2, %3}], [%4];"
        :: "r"(smem_addr), "l"(tmap), "r"(cx), "r"(cy), "r"(mbar) : "memory");
}

// Multicast 2D TMA: deliver the same slice (and complete_tx) to every CTA in mask.
__device__ __forceinline__ void tma_ld2_mc(uint32_t smem_addr, const CUtensorMap* tmap,
                                           int cx, int cy, uint32_t mbar, uint16_t mask) {
    asm volatile(
        "cp.async.bulk.tensor.2d.shared::cluster.global.tile.mbarrier::complete_tx::bytes.multicast::cluster "
        "[%0], [%1, {%2, %3}], [%4], %5;"
        :: "r"(smem_addr), "l"(tmap), "r"(cx), "r"(cy), "r"(mbar), "h"(mask) : "memory");
}
#endif

// ---------------------------------------------------------------------------
// Fallback helpers: ldmatrix + int8 mma.sync (family-portable)
// ---------------------------------------------------------------------------
__device__ __forceinline__ void ldsm_x4(uint32_t& r0, uint32_t& r1,
                                        uint32_t& r2, uint32_t& r3, uint32_t addr) {
    asm volatile("ldmatrix.sync.aligned.m8n8.x4.shared.b16 {%0,%1,%2,%3}, [%4];"
                 : "=r"(r0), "=r"(r1), "=r"(r2), "=r"(r3) : "r"(addr));
}

__device__ __forceinline__ void imma16832(int* c, const uint32_t* a, const uint32_t* b) {
    asm volatile(
        "mma.sync.aligned.m16n8k32.row.col.s32.s8.s8.s32 "
        "{%0,%1,%2,%3}, {%4,%5,%6,%7}, {%8,%9}, {%0,%1,%2,%3};"
        : "+r"(c[0]), "+r"(c[1]), "+r"(c[2]), "+r"(c[3])
        : "r"(a[0]), "r"(a[1]), "r"(a[2]), "r"(a[3]), "r"(b[0]), "r"(b[1]));
}

// ---------------------------------------------------------------------------
// Pre-pass: int32 -> bf16 (tcgen05 path) or int8 (fallback path)
// ---------------------------------------------------------------------------
__global__ void cvt_kernel(const int4* __restrict__ in, void* __restrict__ out, int n4) {
    int i = blockIdx.x * blockDim.x + threadIdx.x;
    if (i >= n4) return;
    int4 v = in[i];
#if HAS_TCGEN05
    __nv_bfloat162 p0, p1;
    p0.x = __int2bfloat16_rn(v.x); p0.y = __int2bfloat16_rn(v.y);
    p1.x = __int2bfloat16_rn(v.z); p1.y = __int2bfloat16_rn(v.w);
    uint2 o;
    o.x = *reinterpret_cast<unsigned*>(&p0);
    o.y = *reinterpret_cast<unsigned*>(&p1);
    reinterpret_cast<uint2*>(out)[i] = o;
#else
    char4 o;
    o.x = (char)v.x; o.y = (char)v.y; o.z = (char)v.z; o.w = (char)v.w;
    reinterpret_cast<char4*>(out)[i] = o;
#endif
}

// ---------------------------------------------------------------------------
// GEMM kernel: 2-CTA cluster, B multicast, 2-stage pipeline, 2 CTAs/SM
// ---------------------------------------------------------------------------
__global__ void __launch_bounds__(GTHREADS) __cluster_dims__(CLUSTER, 1, 1)
q8gemm_kernel(
    const __grid_constant__ CUtensorMap tmA,
    const __grid_constant__ CUtensorMap tmB,
    const float* __restrict__ bias,
    const float* __restrict__ xsc,
    const float* __restrict__ wsc,
    float* __restrict__ out)
{
    extern __shared__ __align__(1024) char smem[];
    const int tid = threadIdx.x;
    const int wid = tid >> 5;
    const int lid = tid & 31;

    // Cluster pair = adjacent m-tiles sharing one n-tile (B multicast group).
    // Band rasterization keeps a 16-n-tile B band L2-resident.
    const int TM_P  = (TOKENS / TILE_M) / CLUSTER;   // 32 m-pairs
    const int GROUP = 16;
    const int rank  = blockIdx.x & 1;                // == cluster_ctarank
    const int pair  = blockIdx.x >> 1;
    const int band  = pair / (GROUP * TM_P);
    const int r     = pair % (GROUP * TM_P);
    const int mtp   = r / GROUP;
    const int nt    = band * GROUP + (r % GROUP);
    const int m0    = (mtp * CLUSTER + rank) * TILE_M;
    const int n0    = nt * TILE_N;

#if HAS_TCGEN05
    // ======================= tcgen05 bf16 + B-multicast path =======================
    const uint32_t sb = smem_u32(smem);

    if (wid == 0) TCGEN05_ALLOC(sb + SM_TMEMPTR, 256);
    if (tid == 0) {
        #pragma unroll
        for (int s = 0; s < NSTAGE; s++) {
            MBARRIER_INIT(sb + SM_FULL(s), 1);   // expect_tx arrival only
            MBARRIER_INIT(sb + SM_DONE(s), 2);   // multicast commits from BOTH CTAs
        }
        MBARRIER_INIT(sb + SM_FINAL, 1);
    }
    __syncthreads();
    // Both CTAs' barriers must be live before any multicast TMA targets them.
    CLUSTER_SYNC();

    uint32_t tbase;
    asm volatile("ld.shared.b32 %0, [%1];" : "=r"(tbase) : "r"(sb + SM_TMEMPTR));

    if (wid == 0) {
        if (elect_one_pred()) {
            #pragma unroll
            for (int s = 0; s < NSTAGE; s++) {
                MBARRIER_EXPECT_TX(sb + SM_FULL(s), STAGE_BYTES);
                tma_ld2(sb + SM_A(s), &tmA, s * KC, m0, sb + SM_FULL(s));
                // This CTA loads B rows [n0 + rank*128, +128) and multicasts the
                // slice to both CTAs; two slices sum to B_BYTES on each barrier.
                tma_ld2_mc(sb + SM_B(s) + rank * B_HALF, &tmB,
                           s * KC, n0 + rank * (TILE_N / 2), sb + SM_FULL(s), 0x3);
            }
        }
        for (int ks = 0; ks < NKI; ks++) {
            const int st = ks & (NSTAGE - 1);
            MBARRIER_WAIT_PARITY(sb + SM_FULL(st), (ks / NSTAGE) & 1);
            if (elect_one_pred()) {
                uint64_t ad = make_desc(sb + SM_A(st));
                uint64_t bd = make_desc(sb + SM_B(st));
                #pragma unroll
                for (int j = 0; j < 4; j++)            // 4 x K16 MMAs = K64
                    mma_bf16_ss(tbase, ad + j * 2, bd + j * 2, MMA_IDESC,
                                (uint32_t)((ks | j) != 0));
                // DONE must see BOTH CTAs' completion before anyone refills this
                // stage (refill multicasts into the peer's SMEM too).
                TCGEN05_COMMIT_MC(sb + SM_DONE(st), 0x3);
            }
            if (ks >= 1 && ks <= NKI - NSTAGE) {
                const int p = (ks - 1) & (NSTAGE - 1);
                MBARRIER_WAIT_PARITY(sb + SM_DONE(p), ((ks - 1) / NSTAGE) & 1);
                if (elect_one_pred()) {
                    MBARRIER_EXPECT_TX(sb + SM_FULL(p), STAGE_BYTES);
                    const int kk = ks - 1 + NSTAGE;
                    tma_ld2(sb + SM_A(p), &tmA, kk * KC, m0, sb + SM_FULL(p));
                    tma_ld2_mc(sb + SM_B(p) + rank * B_HALF, &tmB,
                               kk * KC, n0 + rank * (TILE_N / 2), sb + SM_FULL(p), 0x3);
                }
            }
        }
        if (elect_one_pred()) TCGEN05_COMMIT(sb + SM_FINAL);
    }

    // Epilogue: all 4 warps
    MBARRIER_WAIT_PARITY(sb + SM_FINAL, 0);
    TCGEN05_FENCE_AFTER();

    float* s_ws = reinterpret_cast<float*>(smem + SM_TILES);
    float* s_bi = s_ws + TILE_N;
    for (int i = tid; i < TILE_N; i += GTHREADS) {
        s_ws[i] = wsc[n0 + i];
        s_bi[i] = bias[n0 + i];
    }
    __syncthreads();

    const int row = m0 + wid * 32 + lid;
    const float xsv = xsc[row];
    float* orow = out + (size_t)row * OUT_F + n0;

    #pragma unroll 1
    for (int cb = 0; cb < TILE_N / 32; cb++) {
        uint32_t rg[32];
        TCGEN05_LD_32X32B_X32(rg, tbase + cb * 32);
        TCGEN05_WAIT_LD();
        #pragma unroll
        for (int q = 0; q < 8; q++) {
            const int c = cb * 32 + q * 4;
            float4 v;
            v.x = fmaf(__uint_as_float(rg[q * 4 + 0]), xsv * s_ws[c + 0], s_bi[c + 0]);
            v.y = fmaf(__uint_as_float(rg[q * 4 + 1]), xsv * s_ws[c + 1], s_bi[c + 1]);
            v.z = fmaf(__uint_as_float(rg[q * 4 + 2]), xsv * s_ws[c + 2], s_bi[c + 2]);
            v.w = fmaf(__uint_as_float(rg[q * 4 + 3]), xsv * s_ws[c + 3], s_bi[c + 3]);
            *reinterpret_cast<float4*>(orow + c) = v;
        }
    }
    TCGEN05_FENCE_BEFORE();
    __syncthreads();
    if (wid == 0) {
        TCGEN05_RELINQUISH();
        TCGEN05_DEALLOC(tbase, 256);
    }
    // No CTA may exit while a peer's multicast into its SMEM could be in flight.
    CLUSTER_SYNC();

#else
    // =================== portable int8 mma.sync fallback ===================
    const int8_t* x8 = reinterpret_cast<const int8_t*>(g_xb);
    const int8_t* w8 = reinterpret_cast<const int8_t*>(g_wb);

    const int AST = 80, BST = 80;
    char* sA = smem;
    char* sB = smem + 128 * AST;
    const uint32_t sAu = smem_u32(sA);
    const uint32_t sBu = smem_u32(sB);

    const int warp_row = wid * 32;

    for (int nc = 0; nc < 4; nc++) {
        const int nb = n0 + nc * 64;
        int acc[2][8][4];
        #pragma unroll
        for (int a = 0; a < 2; a++)
            #pragma unroll
            for (int b = 0; b < 8; b++)
                #pragma unroll
                for (int c = 0; c < 4; c++) acc[a][b][c] = 0;

        for (int kt = 0; kt < 64; kt++) {
            const int k0 = kt * 64;
            __syncthreads();
            {
                const uint4* src = reinterpret_cast<const uint4*>(
                    x8 + (size_t)(m0 + tid) * IN_F + k0);
                uint4* dst = reinterpret_cast<uint4*>(sA + tid * AST);
                #pragma unroll
                for (int j = 0; j < 4; j++) dst[j] = src[j];
            }
            {
                const int br = tid >> 1, h = tid & 1;
                const uint4* src = reinterpret_cast<const uint4*>(
                    w8 + (size_t)(nb + br) * IN_F + k0 + h * 32);
                uint4* dst = reinterpret_cast<uint4*>(sB + br * BST + h * 32);
                dst[0] = src[0]; dst[1] = src[1];
            }
            __syncthreads();

            #pragma unroll
            for (int s = 0; s < 2; s++) {
                uint32_t afr[2][4];
                #pragma unroll
                for (int mt2 = 0; mt2 < 2; mt2++) {
                    uint32_t addr = sAu +
                        (uint32_t)(warp_row + mt2 * 16 + (lid & 15)) * AST +
                        s * 32 + ((lid >= 16) ? 16 : 0);
                    ldsm_x4(afr[mt2][0], afr[mt2][1], afr[mt2][2], afr[mt2][3], addr);
                }
                uint32_t bfr[4][4];
                #pragma unroll
                for (int p = 0; p < 4; p++) {
                    uint32_t addr = sBu +
                        (uint32_t)(p * 16 + (lid & 7) + ((lid >= 16) ? 8 : 0)) * BST +
                        s * 32 + ((lid & 8) ? 16 : 0);
                    ldsm_x4(bfr[p][0], bfr[p][1], bfr[p][2], bfr[p][3], addr);
                }
                #pragma unroll
                for (int mt2 = 0; mt2 < 2; mt2++)
                    #pragma unroll
                    for (int nt2 = 0; nt2 < 8; nt2++) {
                        uint32_t bb[2];
                        bb[0] = bfr[nt2 >> 1][(nt2 & 1) ? 2 : 0];
                        bb[1] = bfr[nt2 >> 1][(nt2 & 1) ? 3 : 1];
                        imma16832(acc[mt2][nt2], afr[mt2], bb);
                    }
            }
        }
        #pragma unroll
        for (int mt2 = 0; mt2 < 2; mt2++) {
            const int r0_ = m0 + warp_row + mt2 * 16 + (lid >> 2);
            const float xs0 = xsc[r0_], xs1 = xsc[r0_ + 8];
            #pragma unroll
            for (int nt2 = 0; nt2 < 8; nt2++) {
                const int c0 = nb + nt2 * 8 + (lid & 3) * 2;
                const float w0 = wsc[c0], w1 = wsc[c0 + 1];
                const float b0 = bias[c0], b1 = bias[c0 + 1];
                float* o0 = out + (size_t)r0_ * OUT_F + c0;
                float* o1 = out + (size_t)(r0_ + 8) * OUT_F + c0;
                o0[0] = fmaf((float)acc[mt2][nt2][0], xs0 * w0, b0);
                o0[1] = fmaf((float)acc[mt2][nt2][1], xs0 * w1, b1);
                o1[0] = fmaf((float)acc[mt2][nt2][2], xs1 * w0, b0);
                o1[1] = fmaf((float)acc[mt2][nt2][3], xs1 * w1, b1);
            }
        }
    }
#endif
}

// ---------------------------------------------------------------------------
// Host launcher
// ---------------------------------------------------------------------------
typedef CUresult (*tmencode_fn_t)(
    CUtensorMap*, CUtensorMapDataType, cuuint32_t, void*,
    const cuuint64_t*, const cuuint64_t*, const cuuint32_t*, const cuuint32_t*,
    CUtensorMapInterleave, CUtensorMapSwizzle, CUtensorMapL2promotion,
    CUtensorMapFloatOOBfill);

extern "C" void kernel_launch(void* const* d_in, const int* in_sizes, int n_in,
                              void* d_out, int out_size) {
    const int*   x    = (const int*)d_in[0];
    const int*   w    = (const int*)d_in[1];
    const float* bias = (const float*)d_in[2];
    const float* xsc  = (const float*)d_in[3];
    const float* wsc  = (const float*)d_in[4];
    float* out = (float*)d_out;

    void* xb_ptr = nullptr;
    void* wb_ptr = nullptr;
    cudaGetSymbolAddress(&xb_ptr, g_xb);
    cudaGetSymbolAddress(&wb_ptr, g_wb);

    // Pre-pass: int32 -> (bf16 | int8), matching whichever GEMM variant loads.
    {
        int n4x = TOKENS * IN_F / 4;
        int n4w = OUT_F * IN_F / 4;
        cvt_kernel<<<(n4x + 255) / 256, 256>>>((const int4*)x, xb_ptr, n4x);
        cvt_kernel<<<(n4w + 255) / 256, 256>>>((const int4*)w, wb_ptr, n4w);
    }

    // TMA descriptors (bf16 layout; unused by the fallback variant).
    tmencode_fn_t enc = nullptr;
    {
        void* fn = nullptr;
        cudaDriverEntryPointQueryResult qres;
#if CUDART_VERSION >= 12050
        cudaGetDriverEntryPointByVersion("cuTensorMapEncodeTiled", &fn, 12000,
                                         cudaEnableDefault, &qres);
#else
        cudaGetDriverEntryPoint("cuTensorMapEncodeTiled", &fn,
                                cudaEnableDefault, &qres);
#endif
        enc = (tmencode_fn_t)fn;
    }

    alignas(64) CUtensorMap tmA, tmB;
    if (enc) {
        {
            cuuint64_t dims[2] = {IN_F, TOKENS};
            cuuint64_t strd[1] = {IN_F * 2ull};
            cuuint32_t box[2]  = {KC, TILE_M};          // 128B inner, 128 rows
            cuuint32_t es[2]   = {1, 1};
            enc(&tmA, CU_TENSOR_MAP_DATA_TYPE_BFLOAT16, 2, xb_ptr, dims, strd, box, es,
                CU_TENSOR_MAP_INTERLEAVE_NONE, CU_TENSOR_MAP_SWIZZLE_128B,
                CU_TENSOR_MAP_L2_PROMOTION_L2_128B, CU_TENSOR_MAP_FLOAT_OOB_FILL_NONE);
        }
        {
            cuuint64_t dims[2] = {IN_F, OUT_F};
            cuuint64_t strd[1] = {IN_F * 2ull};
            cuuint32_t box[2]  = {KC, TILE_N / 2};      // one multicast slice = 128 rows
            cuuint32_t es[2]   = {1, 1};
            enc(&tmB, CU_TENSOR_MAP_DATA_TYPE_BFLOAT16, 2, wb_ptr, dims, strd, box, es,
                CU_TENSOR_MAP_INTERLEAVE_NONE, CU_TENSOR_MAP_SWIZZLE_128B,
                CU_TENSOR_MAP_L2_PROMOTION_L2_128B, CU_TENSOR_MAP_FLOAT_OOB_FILL_NONE);
        }
    }

    cudaFuncSetAttribute(q8gemm_kernel,
                         cudaFuncAttributeMaxDynamicSharedMemorySize, SMEM_TOTAL);

    const int grid = (TOKENS / TILE_M) * (OUT_F / TILE_N);  // 4096 (cluster-pairs: 2048)
    q8gemm_kernel<<<grid, GTHREADS, SMEM_TOTAL>>>(tmA, tmB, bias, xsc, wsc, out);
}

// round 9
// speedup vs baseline: 1.8699x; 1.8699x over previous
#include <cuda_runtime.h>
#include <cuda.h>
#include <cuda_bf16.h>
#include <cstdint>

// ---------------------------------------------------------------------------
// Problem constants
// ---------------------------------------------------------------------------
#define TOKENS 8192
#define IN_F   4096
#define OUT_F  16384

#define TILE_M 256                   // two 128-row halves per CTA
#define TILE_N 256
#define GTHREADS 128

// bf16 tcgen05 path: 64 bf16 per stage-row (128B = SW128 atom)
#define KC     64
#define NKI    (IN_F / KC)           // 64 K-iterations
#define NSTAGE 3

// Shared memory layout (tcgen05 path, dynamic)
#define SM_TMEMPTR 0
#define SM_FULL(s) (64 + (s) * 8)
#define SM_DONE(s) (96 + (s) * 8)
#define SM_FINAL   128
#define SM_TILES   1024
#define A_BYTES    (TILE_M * KC * 2)          // 32768 (256 rows)
#define A_HALF     (A_BYTES / 2)              // 16384
#define B_BYTES    (TILE_N * KC * 2)          // 32768
#define STAGE_BYTES (A_BYTES + B_BYTES)       // 65536
#define SM_A(s) (SM_TILES + (s) * STAGE_BYTES)
#define SM_B(s) (SM_A(s) + A_BYTES)
#define SMEM_TOTAL (SM_TILES + NSTAGE * STAGE_BYTES)  // 197632 (1 CTA/SM)

// Arch-specific feature gate: tcgen05 legal only on sm_100a / sm_103a targets.
#if defined(__CUDA_ARCH_FEAT_SM103_ALL) || defined(__CUDA_ARCH_FEAT_SM100_ALL)
#define HAS_TCGEN05 1
#else
#define HAS_TCGEN05 0
#endif

// idesc for kind::f16: dtype=F32 (bit4), atype=BF16 (bit7), btype=BF16 (bit10),
// N/8 at bit17, M/16 at bit24. Each MMA is M=128 (one half), N=256.
static constexpr uint32_t MMA_IDESC =
    (1u << 4) | (1u << 7) | (1u << 10) |
    ((TILE_N / 8u) << 17) | ((128u / 16u) << 24);

// Scratch (device-global scratch is the sanctioned no-alloc path).
// tcgen05 path: bf16. Fallback path: reinterpreted as int8.
__device__ __nv_bfloat16 g_xb[(size_t)TOKENS * IN_F];   // 64 MB
__device__ __nv_bfloat16 g_wb[(size_t)OUT_F * IN_F];    // 128 MB

// ---------------------------------------------------------------------------
// Common PTX helpers
// ---------------------------------------------------------------------------
__device__ __forceinline__ uint32_t elect_one_pred() {
    uint32_t pred;
    asm volatile(
        "{\n\t.reg .pred p;\n\telect.sync _|p, 0xFFFFFFFF;\n\t"
        "selp.b32 %0, 1, 0, p;\n\t}" : "=r"(pred));
    return pred;
}

__device__ __forceinline__ uint32_t smem_u32(const void* p) {
    uint32_t a;
    asm("{ .reg .u64 t; cvta.to.shared.u64 t, %1; cvt.u32.u64 %0, t; }"
        : "=r"(a) : "l"(p));
    return a;
}

#define MBARRIER_INIT(addr, cnt) \
    asm volatile("mbarrier.init.shared.b64 [%0], %1;" :: "r"((uint32_t)(addr)), "r"((uint32_t)(cnt)) : "memory")

#define MBARRIER_EXPECT_TX(addr, tx) \
    asm volatile("mbarrier.arrive.expect_tx.shared.b64 _, [%0], %1;" :: "r"((uint32_t)(addr)), "r"((uint32_t)(tx)) : "memory")

#define MBARRIER_WAIT_PARITY(mbar_smem_addr, phase_parity) do { \
    uint32_t _mbar = (uint32_t)(mbar_smem_addr); \
    uint32_t _parity = (uint32_t)(phase_parity); \
    uint32_t _done_; \
    asm volatile( \
        "{\n\t.reg .pred p;\n\t" \
        "mbarrier.try_wait.parity.acquire.cta.shared::cta.b64 p, [%1], %2;\n\t" \
        "selp.b32 %0, 1, 0, p;\n\t}" \
        : "=r"(_done_) : "r"(_mbar), "r"(_parity) : "memory"); \
    if (!_done_) { \
        asm volatile( \
            "{\n\t.reg .pred P1;\n\t" \
            "WAIT_LOOP_%=:\n\t" \
            "mbarrier.try_wait.parity.acquire.cta.shared::cta.b64 P1, [%0], %1, 0x989680;\n\t" \
            "@P1 bra.uni WAIT_DONE_%=;\n\t" \
            "bra.uni WAIT_LOOP_%=;\n\t" \
            "WAIT_DONE_%=:\n\t}" \
            :: "r"(_mbar), "r"(_parity) : "memory"); \
    } \
} while (0)

// ---------------------------------------------------------------------------
// tcgen05 macros (only EXPANDED inside HAS_TCGEN05 regions)
// ---------------------------------------------------------------------------
#define TCGEN05_ALLOC(smem_result_addr, nCols) \
    asm volatile("tcgen05.alloc.cta_group::1.sync.aligned.shared::cta.b32 [%0], %1;" \
        :: "r"((uint32_t)(smem_result_addr)), "r"((uint32_t)(nCols)) : "memory")

#define TCGEN05_DEALLOC(tmem_addr, nCols) \
    asm volatile("tcgen05.dealloc.cta_group::1.sync.aligned.b32 %0, %1;" \
        :: "r"(tmem_addr), "r"((uint32_t)(nCols)))

#define TCGEN05_RELINQUISH() \
    asm volatile("tcgen05.relinquish_alloc_permit.cta_group::1.sync.aligned;")

#define TCGEN05_COMMIT(mbar_smem_addr) \
    asm volatile("tcgen05.commit.cta_group::1.mbarrier::arrive::one.shared::cluster.b64 [%0];" \
        :: "r"((uint32_t)(mbar_smem_addr)) : "memory")

#define TCGEN05_WAIT_LD() \
    asm volatile("tcgen05.wait::ld.sync.aligned;" ::: "memory")

#define TCGEN05_FENCE_BEFORE() \
    asm volatile("tcgen05.fence::before_thread_sync;" ::: "memory")

#define TCGEN05_FENCE_AFTER() \
    asm volatile("tcgen05.fence::after_thread_sync;" ::: "memory")

#define TCGEN05_LD_32X32B_X32(r, tmem_addr) \
    asm volatile( \
        "tcgen05.ld.sync.aligned.32x32b.x32.b32 " \
        "{%0, %1, %2, %3, %4, %5, %6, %7, " \
        " %8, %9, %10, %11, %12, %13, %14, %15, " \
        " %16, %17, %18, %19, %20, %21, %22, %23, " \
        " %24, %25, %26, %27, %28, %29, %30, %31}, [%32];" \
        : "=r"((r)[0]),  "=r"((r)[1]),  "=r"((r)[2]),  "=r"((r)[3]), \
          "=r"((r)[4]),  "=r"((r)[5]),  "=r"((r)[6]),  "=r"((r)[7]), \
          "=r"((r)[8]),  "=r"((r)[9]),  "=r"((r)[10]), "=r"((r)[11]), \
          "=r"((r)[12]), "=r"((r)[13]), "=r"((r)[14]), "=r"((r)[15]), \
          "=r"((r)[16]), "=r"((r)[17]), "=r"((r)[18]), "=r"((r)[19]), \
          "=r"((r)[20]), "=r"((r)[21]), "=r"((r)[22]), "=r"((r)[23]), \
          "=r"((r)[24]), "=r"((r)[25]), "=r"((r)[26]), "=r"((r)[27]), \
          "=r"((r)[28]), "=r"((r)[29]), "=r"((r)[30]), "=r"((r)[31]) \
        : "r"(tmem_addr))

// SW128 K-major descriptor (LBO=1, SBO=64, version=1, layout=SW128)
static constexpr unsigned long long SMEM_DESC_BASE_SW128 =
    (2ull << 61) | (1ull << 46) | (64ull << 32) | (1ull << 16);

__device__ __forceinline__ uint64_t make_desc(uint32_t smem_addr) {
    return SMEM_DESC_BASE_SW128 | ((uint64_t)(smem_addr >> 4) & 0x3FFFull);
}

#if HAS_TCGEN05
__device__ __forceinline__ void mma_bf16_ss(uint32_t d_tmem, uint64_t a_desc,
                                            uint64_t b_desc, uint32_t idesc,
                                            uint32_t enable_d) {
    asm volatile(
        "{\n\t.reg .pred p;\n\t"
        "setp.ne.u32 p, %5, 0;\n\t"
        "tcgen05.mma.cta_group::1.kind::f16 [%0], %1, %2, %3, {%4, %4, %4, %4}, p;\n\t}"
        :: "r"(d_tmem), "l"(a_desc), "l"(b_desc), "r"(idesc), "r"(0u), "r"(enable_d)
        : "memory");
}

__device__ __forceinline__ void tma_ld2(uint32_t smem_addr, const CUtensorMap* tmap,
                                        int cx, int cy, uint32_t mbar) {
    asm volatile(
        "cp.async.bulk.tensor.2d.shared::cta.global.tile.mbarrier::complete_tx::bytes "
        "[%0], [%1, {%2, %3}], [%4];"
        :: "r"(smem_addr), "l"(tmap), "r"(cx), "r"(cy), "r"(mbar) : "memory");
}
#endif

// ---------------------------------------------------------------------------
// Fallback helpers: ldmatrix + int8 mma.sync (family-portable)
// ---------------------------------------------------------------------------
__device__ __forceinline__ void ldsm_x4(uint32_t& r0, uint32_t& r1,
                                        uint32_t& r2, uint32_t& r3, uint32_t addr) {
    asm volatile("ldmatrix.sync.aligned.m8n8.x4.shared.b16 {%0,%1,%2,%3}, [%4];"
                 : "=r"(r0), "=r"(r1), "=r"(r2), "=r"(r3) : "r"(addr));
}

__device__ __forceinline__ void imma16832(int* c, const uint32_t* a, const uint32_t* b) {
    asm volatile(
        "mma.sync.aligned.m16n8k32.row.col.s32.s8.s8.s32 "
        "{%0,%1,%2,%3}, {%4,%5,%6,%7}, {%8,%9}, {%0,%1,%2,%3};"
        : "+r"(c[0]), "+r"(c[1]), "+r"(c[2]), "+r"(c[3])
        : "r"(a[0]), "r"(a[1]), "r"(a[2]), "r"(a[3]), "r"(b[0]), "r"(b[1]));
}

// ---------------------------------------------------------------------------
// Pre-pass: int32 -> bf16 (tcgen05 path) or int8 (fallback path)
// ---------------------------------------------------------------------------
__global__ void cvt_kernel(const int4* __restrict__ in, void* __restrict__ out, int n4) {
    int i = blockIdx.x * blockDim.x + threadIdx.x;
    if (i >= n4) return;
    int4 v = in[i];
#if HAS_TCGEN05
    __nv_bfloat162 p0, p1;
    p0.x = __int2bfloat16_rn(v.x); p0.y = __int2bfloat16_rn(v.y);
    p1.x = __int2bfloat16_rn(v.z); p1.y = __int2bfloat16_rn(v.w);
    uint2 o;
    o.x = *reinterpret_cast<unsigned*>(&p0);
    o.y = *reinterpret_cast<unsigned*>(&p1);
    reinterpret_cast<uint2*>(out)[i] = o;
#else
    char4 o;
    o.x = (char)v.x; o.y = (char)v.y; o.z = (char)v.z; o.w = (char)v.w;
    reinterpret_cast<char4*>(out)[i] = o;
#endif
}

// ---------------------------------------------------------------------------
// GEMM: 256x256 per CTA (two M-halves share each B stage), 3-stage pipeline.
// No clusters, no cross-CTA dependencies (lesson from R8).
// ---------------------------------------------------------------------------
__global__ void __launch_bounds__(GTHREADS) q8gemm_kernel(
    const __grid_constant__ CUtensorMap tmA,
    const __grid_constant__ CUtensorMap tmB,
    const float* __restrict__ bias,
    const float* __restrict__ xsc,
    const float* __restrict__ wsc,
    float* __restrict__ out)
{
    extern __shared__ __align__(1024) char smem[];
    const int tid = threadIdx.x;
    const int wid = tid >> 5;
    const int lid = tid & 31;

    // Band rasterization: 16-n-tile bands (32MB of B) stay L2-resident while
    // all 32 m-supertiles sweep.
    const int TM_T  = TOKENS / TILE_M;    // 32
    const int GROUP = 16;
    int bid  = blockIdx.x;
    int band = bid / (GROUP * TM_T);
    int r    = bid % (GROUP * TM_T);
    int mt   = r / GROUP;
    int nt   = band * GROUP + (r % GROUP);
    const int m0 = mt * TILE_M;           // 256 rows
    const int n0 = nt * TILE_N;

#if HAS_TCGEN05
    // ======================= tcgen05 bf16 path =======================
    const uint32_t sb = smem_u32(smem);

    if (wid == 0) TCGEN05_ALLOC(sb + SM_TMEMPTR, 512);   // D0 (256) + D1 (256)
    if (tid == 0) {
        #pragma unroll
        for (int s = 0; s < NSTAGE; s++) {
            MBARRIER_INIT(sb + SM_FULL(s), 1);
            MBARRIER_INIT(sb + SM_DONE(s), 1);
        }
        MBARRIER_INIT(sb + SM_FINAL, 1);
    }
    __syncthreads();

    uint32_t tbase;
    asm volatile("ld.shared.b32 %0, [%1];" : "=r"(tbase) : "r"(sb + SM_TMEMPTR));

    if (wid == 0) {
        if (elect_one_pred()) {
            #pragma unroll
            for (int s = 0; s < NSTAGE; s++) {
                MBARRIER_EXPECT_TX(sb + SM_FULL(s), STAGE_BYTES);
                tma_ld2(sb + SM_A(s), &tmA, s * KC, m0, sb + SM_FULL(s)); // 256 rows
                tma_ld2(sb + SM_B(s), &tmB, s * KC, n0, sb + SM_FULL(s)); // 256 rows
            }
        }
        // Incremental stage/phase cursors (NSTAGE=3 is not a power of two).
        int st = 0, ph = 0;        // current iteration's stage/phase
        int pst = 0, pph = 0;      // previous iteration's stage/phase
        for (int ks = 0; ks < NKI; ks++) {
            MBARRIER_WAIT_PARITY(sb + SM_FULL(st), ph);
            if (elect_one_pred()) {
                uint64_t a0 = make_desc(sb + SM_A(st));           // rows 0-127
                uint64_t a1 = make_desc(sb + SM_A(st) + A_HALF);  // rows 128-255
                uint64_t bd = make_desc(sb + SM_B(st));
                const uint32_t en = (uint32_t)(ks != 0);
                #pragma unroll
                for (int j = 0; j < 4; j++) {          // 4 x K16 per half = K64
                    uint32_t e = en | (uint32_t)(j != 0);
                    mma_bf16_ss(tbase,       a0 + j * 2, bd + j * 2, MMA_IDESC, e);
                    mma_bf16_ss(tbase + 256, a1 + j * 2, bd + j * 2, MMA_IDESC, e);
                }
                TCGEN05_COMMIT(sb + SM_DONE(st));
            }
            // Refill the stage used LAST iteration (its MMAs finish before ours,
            // which are queued behind — tensor pipe never drains on the wait).
            if (ks >= 1 && ks <= NKI - NSTAGE) {
                MBARRIER_WAIT_PARITY(sb + SM_DONE(pst), pph);
                if (elect_one_pred()) {
                    MBARRIER_EXPECT_TX(sb + SM_FULL(pst), STAGE_BYTES);
                    const int kk = ks - 1 + NSTAGE;
                    tma_ld2(sb + SM_A(pst), &tmA, kk * KC, m0, sb + SM_FULL(pst));
                    tma_ld2(sb + SM_B(pst), &tmB, kk * KC, n0, sb + SM_FULL(pst));
                }
            }
            pst = st; pph = ph;
            if (++st == NSTAGE) { st = 0; ph ^= 1; }
        }
        if (elect_one_pred()) TCGEN05_COMMIT(sb + SM_FINAL);
    }

    // Epilogue: all 4 warps, both M-halves.
    MBARRIER_WAIT_PARITY(sb + SM_FINAL, 0);
    TCGEN05_FENCE_AFTER();

    float* s_ws = reinterpret_cast<float*>(smem + SM_TILES);
    float* s_bi = s_ws + TILE_N;
    for (int i = tid; i < TILE_N; i += GTHREADS) {
        s_ws[i] = wsc[n0 + i];
        s_bi[i] = bias[n0 + i];
    }
    __syncthreads();

    #pragma unroll 1
    for (int h = 0; h < 2; h++) {
        const int row = m0 + h * 128 + wid * 32 + lid;
        const float xsv = xsc[row];
        float* orow = out + (size_t)row * OUT_F + n0;
        #pragma unroll 1
        for (int cb = 0; cb < TILE_N / 32; cb++) {
            uint32_t rg[32];
            TCGEN05_LD_32X32B_X32(rg, tbase + h * 256 + cb * 32);
            TCGEN05_WAIT_LD();
            #pragma unroll
            for (int q = 0; q < 8; q++) {
                const int c = cb * 32 + q * 4;
                float4 v;
                v.x = fmaf(__uint_as_float(rg[q * 4 + 0]), xsv * s_ws[c + 0], s_bi[c + 0]);
                v.y = fmaf(__uint_as_float(rg[q * 4 + 1]), xsv * s_ws[c + 1], s_bi[c + 1]);
                v.z = fmaf(__uint_as_float(rg[q * 4 + 2]), xsv * s_ws[c + 2], s_bi[c + 2]);
                v.w = fmaf(__uint_as_float(rg[q * 4 + 3]), xsv * s_ws[c + 3], s_bi[c + 3]);
                *reinterpret_cast<float4*>(orow + c) = v;
            }
        }
    }
    TCGEN05_FENCE_BEFORE();
    __syncthreads();
    if (wid == 0) {
        TCGEN05_RELINQUISH();
        TCGEN05_DEALLOC(tbase, 512);
    }

#else
    // =================== portable int8 mma.sync fallback ===================
    // 256x256 tile handled as two sequential 128-row halves.
    const int8_t* x8 = reinterpret_cast<const int8_t*>(g_xb);
    const int8_t* w8 = reinterpret_cast<const int8_t*>(g_wb);

    const int AST = 80, BST = 80;
    char* sA = smem;
    char* sB = smem + 128 * AST;
    const uint32_t sAu = smem_u32(sA);
    const uint32_t sBu = smem_u32(sB);
    const int warp_row = wid * 32;

    for (int mh = 0; mh < 2; mh++) {
        const int m0h = m0 + mh * 128;
        for (int nc = 0; nc < 4; nc++) {
            const int nb = n0 + nc * 64;
            int acc[2][8][4];
            #pragma unroll
            for (int a = 0; a < 2; a++)
                #pragma unroll
                for (int b = 0; b < 8; b++)
                    #pragma unroll
                    for (int c = 0; c < 4; c++) acc[a][b][c] = 0;

            for (int kt = 0; kt < 64; kt++) {
                const int k0 = kt * 64;
                __syncthreads();
                {
                    const uint4* src = reinterpret_cast<const uint4*>(
                        x8 + (size_t)(m0h + tid) * IN_F + k0);
                    uint4* dst = reinterpret_cast<uint4*>(sA + tid * AST);
                    #pragma unroll
                    for (int j = 0; j < 4; j++) dst[j] = src[j];
                }
                {
                    const int br = tid >> 1, hh = tid & 1;
                    const uint4* src = reinterpret_cast<const uint4*>(
                        w8 + (size_t)(nb + br) * IN_F + k0 + hh * 32);
                    uint4* dst = reinterpret_cast<uint4*>(sB + br * BST + hh * 32);
                    dst[0] = src[0]; dst[1] = src[1];
                }
                __syncthreads();

                #pragma unroll
                for (int s = 0; s < 2; s++) {
                    uint32_t afr[2][4];
                    #pragma unroll
                    for (int mt2 = 0; mt2 < 2; mt2++) {
                        uint32_t addr = sAu +
                            (uint32_t)(warp_row + mt2 * 16 + (lid & 15)) * AST +
                            s * 32 + ((lid >= 16) ? 16 : 0);
                        ldsm_x4(afr[mt2][0], afr[mt2][1], afr[mt2][2], afr[mt2][3], addr);
                    }
                    uint32_t bfr[4][4];
                    #pragma unroll
                    for (int p = 0; p < 4; p++) {
                        uint32_t addr = sBu +
                            (uint32_t)(p * 16 + (lid & 7) + ((lid >= 16) ? 8 : 0)) * BST +
                            s * 32 + ((lid & 8) ? 16 : 0);
                        ldsm_x4(bfr[p][0], bfr[p][1], bfr[p][2], bfr[p][3], addr);
                    }
                    #pragma unroll
                    for (int mt2 = 0; mt2 < 2; mt2++)
                        #pragma unroll
                        for (int nt2 = 0; nt2 < 8; nt2++) {
                            uint32_t bb[2];
                            bb[0] = bfr[nt2 >> 1][(nt2 & 1) ? 2 : 0];
                            bb[1] = bfr[nt2 >> 1][(nt2 & 1) ? 3 : 1];
                            imma16832(acc[mt2][nt2], afr[mt2], bb);
                        }
                }
            }
            #pragma unroll
            for (int mt2 = 0; mt2 < 2; mt2++) {
                const int r0_ = m0h + warp_row + mt2 * 16 + (lid >> 2);
                const float xs0 = xsc[r0_], xs1 = xsc[r0_ + 8];
                #pragma unroll
                for (int nt2 = 0; nt2 < 8; nt2++) {
                    const int c0 = nb + nt2 * 8 + (lid & 3) * 2;
                    const float w0 = wsc[c0], w1 = wsc[c0 + 1];
                    const float b0 = bias[c0], b1 = bias[c0 + 1];
                    float* o0 = out + (size_t)r0_ * OUT_F + c0;
                    float* o1 = out + (size_t)(r0_ + 8) * OUT_F + c0;
                    o0[0] = fmaf((float)acc[mt2][nt2][0], xs0 * w0, b0);
                    o0[1] = fmaf((float)acc[mt2][nt2][1], xs0 * w1, b1);
                    o1[0] = fmaf((float)acc[mt2][nt2][2], xs1 * w0, b0);
                    o1[1] = fmaf((float)acc[mt2][nt2][3], xs1 * w1, b1);
                }
            }
        }
    }
#endif
}

// ---------------------------------------------------------------------------
// Host launcher
// ---------------------------------------------------------------------------
typedef CUresult (*tmencode_fn_t)(
    CUtensorMap*, CUtensorMapDataType, cuuint32_t, void*,
    const cuuint64_t*, const cuuint64_t*, const cuuint32_t*, const cuuint32_t*,
    CUtensorMapInterleave, CUtensorMapSwizzle, CUtensorMapL2promotion,
    CUtensorMapFloatOOBfill);

extern "C" void kernel_launch(void* const* d_in, const int* in_sizes, int n_in,
                              void* d_out, int out_size) {
    const int*   x    = (const int*)d_in[0];
    const int*   w    = (const int*)d_in[1];
    const float* bias = (const float*)d_in[2];
    const float* xsc  = (const float*)d_in[3];
    const float* wsc  = (const float*)d_in[4];
    float* out = (float*)d_out;

    void* xb_ptr = nullptr;
    void* wb_ptr = nullptr;
    cudaGetSymbolAddress(&xb_ptr, g_xb);
    cudaGetSymbolAddress(&wb_ptr, g_wb);

    // Pre-pass: int32 -> (bf16 | int8), matching whichever GEMM variant loads.
    {
        int n4x = TOKENS * IN_F / 4;
        int n4w = OUT_F * IN_F / 4;
        cvt_kernel<<<(n4x + 255) / 256, 256>>>((const int4*)x, xb_ptr, n4x);
        cvt_kernel<<<(n4w + 255) / 256, 256>>>((const int4*)w, wb_ptr, n4w);
    }

    // TMA descriptors (bf16 layout; unused by the fallback variant).
    tmencode_fn_t enc = nullptr;
    {
        void* fn = nullptr;
        cudaDriverEntryPointQueryResult qres;
#if CUDART_VERSION >= 12050
        cudaGetDriverEntryPointByVersion("cuTensorMapEncodeTiled", &fn, 12000,
                                         cudaEnableDefault, &qres);
#else
        cudaGetDriverEntryPoint("cuTensorMapEncodeTiled", &fn,
                                cudaEnableDefault, &qres);
#endif
        enc = (tmencode_fn_t)fn;
    }

    alignas(64) CUtensorMap tmA, tmB;
    if (enc) {
        {
            cuuint64_t dims[2] = {IN_F, TOKENS};
            cuuint64_t strd[1] = {IN_F * 2ull};
            cuuint32_t box[2]  = {KC, TILE_M};          // 128B inner, 256 rows
            cuuint32_t es[2]   = {1, 1};
            enc(&tmA, CU_TENSOR_MAP_DATA_TYPE_BFLOAT16, 2, xb_ptr, dims, strd, box, es,
                CU_TENSOR_MAP_INTERLEAVE_NONE, CU_TENSOR_MAP_SWIZZLE_128B,
                CU_TENSOR_MAP_L2_PROMOTION_L2_128B, CU_TENSOR_MAP_FLOAT_OOB_FILL_NONE);
        }
        {
            cuuint64_t dims[2] = {IN_F, OUT_F};
            cuuint64_t strd[1] = {IN_F * 2ull};
            cuuint32_t box[2]  = {KC, TILE_N};          // 128B inner, 256 rows
            cuuint32_t es[2]   = {1, 1};
            enc(&tmB, CU_TENSOR_MAP_DATA_TYPE_BFLOAT16, 2, wb_ptr, dims, strd, box, es,
                CU_TENSOR_MAP_INTERLEAVE_NONE, CU_TENSOR_MAP_SWIZZLE_128B,
                CU_TENSOR_MAP_L2_PROMOTION_L2_128B, CU_TENSOR_MAP_FLOAT_OOB_FILL_NONE);
        }
    }

    cudaFuncSetAttribute(q8gemm_kernel,
                         cudaFuncAttributeMaxDynamicSharedMemorySize, SMEM_TOTAL);

    const int grid = (TOKENS / TILE_M) * (OUT_F / TILE_N);  // 2048
    q8gemm_kernel<<<grid, GTHREADS, SMEM_TOTAL>>>(tmA, tmB, bias, xsc, wsc, out);
}

// round 10
// speedup vs baseline: 2.0998x; 1.1229x over previous
#include <cuda_runtime.h>
#include <cuda.h>
#include <cuda_bf16.h>
#include <cstdint>

// ---------------------------------------------------------------------------
// Problem constants
// ---------------------------------------------------------------------------
#define TOKENS 8192
#define IN_F   4096
#define OUT_F  16384

#define TILE_M 256                   // two 128-row halves per CTA
#define TILE_N 256
#define GTHREADS 128

// bf16 tcgen05 path: SW64 atoms, 32 bf16 per stage-row (64B rows)
#define KC     32
#define NKI    (IN_F / KC)           // 128 K-iterations
#define NSTAGE 6

// Shared memory layout (tcgen05 path, dynamic)
#define SM_TMEMPTR 0
#define SM_FULL(s) (64  + (s) * 8)   // 64..111
#define SM_DONE(s) (128 + (s) * 8)   // 128..175  (no overlap with FULL)
#define SM_FINAL   192
#define SM_TILES   1024
#define A_BYTES    (TILE_M * KC * 2)          // 16384 (256 rows x 64B)
#define A_HALF     (A_BYTES / 2)              // 8192 (128 rows)
#define B_BYTES    (TILE_N * KC * 2)          // 16384
#define STAGE_BYTES (A_BYTES + B_BYTES)       // 32768
#define SM_A(s) (SM_TILES + (s) * STAGE_BYTES)
#define SM_B(s) (SM_A(s) + A_BYTES)
#define SMEM_TOTAL (SM_TILES + NSTAGE * STAGE_BYTES)  // 197632 (1 CTA/SM)

// Arch-specific feature gate: tcgen05 legal only on sm_100a / sm_103a targets.
#if defined(__CUDA_ARCH_FEAT_SM103_ALL) || defined(__CUDA_ARCH_FEAT_SM100_ALL)
#define HAS_TCGEN05 1
#else
#define HAS_TCGEN05 0
#endif

// idesc for kind::f16: dtype=F32 (bit4), atype=BF16 (bit7), btype=BF16 (bit10),
// N/8 at bit17, M/16 at bit24. Each MMA is M=128 (one half), N=256, K=16.
static constexpr uint32_t MMA_IDESC =
    (1u << 4) | (1u << 7) | (1u << 10) |
    ((TILE_N / 8u) << 17) | ((128u / 16u) << 24);

// Scratch (device-global scratch is the sanctioned no-alloc path).
// tcgen05 path: bf16. Fallback path: reinterpreted as int8.
__device__ __nv_bfloat16 g_xb[(size_t)TOKENS * IN_F];   // 64 MB
__device__ __nv_bfloat16 g_wb[(size_t)OUT_F * IN_F];    // 128 MB

// ---------------------------------------------------------------------------
// Common PTX helpers
// ---------------------------------------------------------------------------
__device__ __forceinline__ uint32_t elect_one_pred() {
    uint32_t pred;
    asm volatile(
        "{\n\t.reg .pred p;\n\telect.sync _|p, 0xFFFFFFFF;\n\t"
        "selp.b32 %0, 1, 0, p;\n\t}" : "=r"(pred));
    return pred;
}

__device__ __forceinline__ uint32_t smem_u32(const void* p) {
    uint32_t a;
    asm("{ .reg .u64 t; cvta.to.shared.u64 t, %1; cvt.u32.u64 %0, t; }"
        : "=r"(a) : "l"(p));
    return a;
}

#define MBARRIER_INIT(addr, cnt) \
    asm volatile("mbarrier.init.shared.b64 [%0], %1;" :: "r"((uint32_t)(addr)), "r"((uint32_t)(cnt)) : "memory")

#define MBARRIER_EXPECT_TX(addr, tx) \
    asm volatile("mbarrier.arrive.expect_tx.shared.b64 _, [%0], %1;" :: "r"((uint32_t)(addr)), "r"((uint32_t)(tx)) : "memory")

#define MBARRIER_WAIT_PARITY(mbar_smem_addr, phase_parity) do { \
    uint32_t _mbar = (uint32_t)(mbar_smem_addr); \
    uint32_t _parity = (uint32_t)(phase_parity); \
    uint32_t _done_; \
    asm volatile( \
        "{\n\t.reg .pred p;\n\t" \
        "mbarrier.try_wait.parity.acquire.cta.shared::cta.b64 p, [%1], %2;\n\t" \
        "selp.b32 %0, 1, 0, p;\n\t}" \
        : "=r"(_done_) : "r"(_mbar), "r"(_parity) : "memory"); \
    if (!_done_) { \
        asm volatile( \
            "{\n\t.reg .pred P1;\n\t" \
            "WAIT_LOOP_%=:\n\t" \
            "mbarrier.try_wait.parity.acquire.cta.shared::cta.b64 P1, [%0], %1, 0x989680;\n\t" \
            "@P1 bra.uni WAIT_DONE_%=;\n\t" \
            "bra.uni WAIT_LOOP_%=;\n\t" \
            "WAIT_DONE_%=:\n\t}" \
            :: "r"(_mbar), "r"(_parity) : "memory"); \
    } \
} while (0)

// ---------------------------------------------------------------------------
// tcgen05 macros (only EXPANDED inside HAS_TCGEN05 regions)
// ---------------------------------------------------------------------------
#define TCGEN05_ALLOC(smem_result_addr, nCols) \
    asm volatile("tcgen05.alloc.cta_group::1.sync.aligned.shared::cta.b32 [%0], %1;" \
        :: "r"((uint32_t)(smem_result_addr)), "r"((uint32_t)(nCols)) : "memory")

#define TCGEN05_DEALLOC(tmem_addr, nCols) \
    asm volatile("tcgen05.dealloc.cta_group::1.sync.aligned.b32 %0, %1;" \
        :: "r"(tmem_addr), "r"((uint32_t)(nCols)))

#define TCGEN05_RELINQUISH() \
    asm volatile("tcgen05.relinquish_alloc_permit.cta_group::1.sync.aligned;")

#define TCGEN05_COMMIT(mbar_smem_addr) \
    asm volatile("tcgen05.commit.cta_group::1.mbarrier::arrive::one.shared::cluster.b64 [%0];" \
        :: "r"((uint32_t)(mbar_smem_addr)) : "memory")

#define TCGEN05_WAIT_LD() \
    asm volatile("tcgen05.wait::ld.sync.aligned;" ::: "memory")

#define TCGEN05_FENCE_BEFORE() \
    asm volatile("tcgen05.fence::before_thread_sync;" ::: "memory")

#define TCGEN05_FENCE_AFTER() \
    asm volatile("tcgen05.fence::after_thread_sync;" ::: "memory")

#define TCGEN05_LD_32X32B_X32(r, tmem_addr) \
    asm volatile( \
        "tcgen05.ld.sync.aligned.32x32b.x32.b32 " \
        "{%0, %1, %2, %3, %4, %5, %6, %7, " \
        " %8, %9, %10, %11, %12, %13, %14, %15, " \
        " %16, %17, %18, %19, %20, %21, %22, %23, " \
        " %24, %25, %26, %27, %28, %29, %30, %31}, [%32];" \
        : "=r"((r)[0]),  "=r"((r)[1]),  "=r"((r)[2]),  "=r"((r)[3]), \
          "=r"((r)[4]),  "=r"((r)[5]),  "=r"((r)[6]),  "=r"((r)[7]), \
          "=r"((r)[8]),  "=r"((r)[9]),  "=r"((r)[10]), "=r"((r)[11]), \
          "=r"((r)[12]), "=r"((r)[13]), "=r"((r)[14]), "=r"((r)[15]), \
          "=r"((r)[16]), "=r"((r)[17]), "=r"((r)[18]), "=r"((r)[19]), \
          "=r"((r)[20]), "=r"((r)[21]), "=r"((r)[22]), "=r"((r)[23]), \
          "=r"((r)[24]), "=r"((r)[25]), "=r"((r)[26]), "=r"((r)[27]), \
          "=r"((r)[28]), "=r"((r)[29]), "=r"((r)[30]), "=r"((r)[31]) \
        : "r"(tmem_addr))

// SW64 K-major descriptor: layout_type=4 (SW64), version=1, SBO=32
// (32*16 = 512B = 8 rows x 64B atom), LBO=1 (16B inner stride).
static constexpr unsigned long long SMEM_DESC_BASE_SW64 =
    (4ull << 61) | (1ull << 46) | (32ull << 32) | (1ull << 16);

__device__ __forceinline__ uint64_t make_desc64(uint32_t smem_addr) {
    return SMEM_DESC_BASE_SW64 | ((uint64_t)(smem_addr >> 4) & 0x3FFFull);
}

#if HAS_TCGEN05
__device__ __forceinline__ void mma_bf16_ss(uint32_t d_tmem, uint64_t a_desc,
                                            uint64_t b_desc, uint32_t idesc,
                                            uint32_t enable_d) {
    asm volatile(
        "{\n\t.reg .pred p;\n\t"
        "setp.ne.u32 p, %5, 0;\n\t"
        "tcgen05.mma.cta_group::1.kind::f16 [%0], %1, %2, %3, {%4, %4, %4, %4}, p;\n\t}"
        :: "r"(d_tmem), "l"(a_desc), "l"(b_desc), "r"(idesc), "r"(0u), "r"(enable_d)
        : "memory");
}

__device__ __forceinline__ void tma_ld2(uint32_t smem_addr, const CUtensorMap* tmap,
                                        int cx, int cy, uint32_t mbar) {
    asm volatile(
        "cp.async.bulk.tensor.2d.shared::cta.global.tile.mbarrier::complete_tx::bytes "
        "[%0], [%1, {%2, %3}], [%4];"
        :: "r"(smem_addr), "l"(tmap), "r"(cx), "r"(cy), "r"(mbar) : "memory");
}
#endif

// ---------------------------------------------------------------------------
// Fallback helpers: ldmatrix + int8 mma.sync (family-portable)
// ---------------------------------------------------------------------------
__device__ __forceinline__ void ldsm_x4(uint32_t& r0, uint32_t& r1,
                                        uint32_t& r2, uint32_t& r3, uint32_t addr) {
    asm volatile("ldmatrix.sync.aligned.m8n8.x4.shared.b16 {%0,%1,%2,%3}, [%4];"
                 : "=r"(r0), "=r"(r1), "=r"(r2), "=r"(r3) : "r"(addr));
}

__device__ __forceinline__ void imma16832(int* c, const uint32_t* a, const uint32_t* b) {
    asm volatile(
        "mma.sync.aligned.m16n8k32.row.col.s32.s8.s8.s32 "
        "{%0,%1,%2,%3}, {%4,%5,%6,%7}, {%8,%9}, {%0,%1,%2,%3};"
        : "+r"(c[0]), "+r"(c[1]), "+r"(c[2]), "+r"(c[3])
        : "r"(a[0]), "r"(a[1]), "r"(a[2]), "r"(a[3]), "r"(b[0]), "r"(b[1]));
}

// ---------------------------------------------------------------------------
// Pre-pass: int32 -> bf16 (tcgen05 path) or int8 (fallback path)
// ---------------------------------------------------------------------------
__global__ void cvt_kernel(const int4* __restrict__ in, void* __restrict__ out, int n4) {
    int i = blockIdx.x * blockDim.x + threadIdx.x;
    if (i >= n4) return;
    int4 v = in[i];
#if HAS_TCGEN05
    __nv_bfloat162 p0, p1;
    p0.x = __int2bfloat16_rn(v.x); p0.y = __int2bfloat16_rn(v.y);
    p1.x = __int2bfloat16_rn(v.z); p1.y = __int2bfloat16_rn(v.w);
    uint2 o;
    o.x = *reinterpret_cast<unsigned*>(&p0);
    o.y = *reinterpret_cast<unsigned*>(&p1);
    reinterpret_cast<uint2*>(out)[i] = o;
#else
    char4 o;
    o.x = (char)v.x; o.y = (char)v.y; o.z = (char)v.z; o.w = (char)v.w;
    reinterpret_cast<char4*>(out)[i] = o;
#endif
}

// ---------------------------------------------------------------------------
// GEMM: 256x256 per CTA, SW64 half-K stages, 6-stage pipeline (depth!).
// No clusters, no cross-CTA dependencies (lesson from R8).
// ---------------------------------------------------------------------------
__global__ void __launch_bounds__(GTHREADS) q8gemm_kernel(
    const __grid_constant__ CUtensorMap tmA,
    const __grid_constant__ CUtensorMap tmB,
    const float* __restrict__ bias,
    const float* __restrict__ xsc,
    const float* __restrict__ wsc,
    float* __restrict__ out)
{
    extern __shared__ __align__(1024) char smem[];
    const int tid = threadIdx.x;
    const int wid = tid >> 5;
    const int lid = tid & 31;

    // Band rasterization: 16-n-tile bands (32MB of B) stay L2-resident while
    // all 32 m-supertiles sweep.
    const int TM_T  = TOKENS / TILE_M;    // 32
    const int GROUP = 16;
    int bid  = blockIdx.x;
    int band = bid / (GROUP * TM_T);
    int r    = bid % (GROUP * TM_T);
    int mt   = r / GROUP;
    int nt   = band * GROUP + (r % GROUP);
    const int m0 = mt * TILE_M;           // 256 rows
    const int n0 = nt * TILE_N;

#if HAS_TCGEN05
    // ======================= tcgen05 bf16 SW64 path =======================
    const uint32_t sb = smem_u32(smem);

    if (wid == 0) TCGEN05_ALLOC(sb + SM_TMEMPTR, 512);   // D0 (256) + D1 (256)
    if (tid == 0) {
        #pragma unroll
        for (int s = 0; s < NSTAGE; s++) {
            MBARRIER_INIT(sb + SM_FULL(s), 1);
            MBARRIER_INIT(sb + SM_DONE(s), 1);
        }
        MBARRIER_INIT(sb + SM_FINAL, 1);
    }
    __syncthreads();

    uint32_t tbase;
    asm volatile("ld.shared.b32 %0, [%1];" : "=r"(tbase) : "r"(sb + SM_TMEMPTR));

    if (wid == 0) {
        if (elect_one_pred()) {
            #pragma unroll
            for (int s = 0; s < NSTAGE; s++) {
                MBARRIER_EXPECT_TX(sb + SM_FULL(s), STAGE_BYTES);
                tma_ld2(sb + SM_A(s), &tmA, s * KC, m0, sb + SM_FULL(s)); // 256 rows
                tma_ld2(sb + SM_B(s), &tmB, s * KC, n0, sb + SM_FULL(s)); // 256 rows
            }
        }
        // Incremental stage/phase cursors (NSTAGE=6 is not a power of two).
        int st = 0, ph = 0;        // current iteration's stage/phase
        int pst = 0, pph = 0;      // previous iteration's stage/phase
        for (int ks = 0; ks < NKI; ks++) {
            MBARRIER_WAIT_PARITY(sb + SM_FULL(st), ph);
            if (elect_one_pred()) {
                uint64_t a0 = make_desc64(sb + SM_A(st));           // rows 0-127
                uint64_t a1 = make_desc64(sb + SM_A(st) + A_HALF);  // rows 128-255
                uint64_t bd = make_desc64(sb + SM_B(st));
                #pragma unroll
                for (int j = 0; j < 2; j++) {          // 2 x K16 per half = K32
                    uint32_t e = (uint32_t)((ks | j) != 0);
                    mma_bf16_ss(tbase,       a0 + j * 2, bd + j * 2, MMA_IDESC, e);
                    mma_bf16_ss(tbase + 256, a1 + j * 2, bd + j * 2, MMA_IDESC, e);
                }
                TCGEN05_COMMIT(sb + SM_DONE(st));
            }
            // Refill the stage used LAST iteration (its MMAs finish before ours,
            // which are queued behind — tensor pipe never drains on the wait).
            // With 6 stages this refill targets consumption 5 iters out, so
            // ~4 refills (128KB) stay in flight.
            if (ks >= 1 && ks <= NKI - NSTAGE) {
                MBARRIER_WAIT_PARITY(sb + SM_DONE(pst), pph);
                if (elect_one_pred()) {
                    MBARRIER_EXPECT_TX(sb + SM_FULL(pst), STAGE_BYTES);
                    const int kk = ks - 1 + NSTAGE;
                    tma_ld2(sb + SM_A(pst), &tmA, kk * KC, m0, sb + SM_FULL(pst));
                    tma_ld2(sb + SM_B(pst), &tmB, kk * KC, n0, sb + SM_FULL(pst));
                }
            }
            pst = st; pph = ph;
            if (++st == NSTAGE) { st = 0; ph ^= 1; }
        }
        if (elect_one_pred()) TCGEN05_COMMIT(sb + SM_FINAL);
    }

    // Epilogue: all 4 warps, both M-halves.
    MBARRIER_WAIT_PARITY(sb + SM_FINAL, 0);
    TCGEN05_FENCE_AFTER();

    float* s_ws = reinterpret_cast<float*>(smem + SM_TILES);
    float* s_bi = s_ws + TILE_N;
    for (int i = tid; i < TILE_N; i += GTHREADS) {
        s_ws[i] = wsc[n0 + i];
        s_bi[i] = bias[n0 + i];
    }
    __syncthreads();

    #pragma unroll 1
    for (int h = 0; h < 2; h++) {
        const int row = m0 + h * 128 + wid * 32 + lid;
        const float xsv = xsc[row];
        float* orow = out + (size_t)row * OUT_F + n0;
        #pragma unroll 1
        for (int cb = 0; cb < TILE_N / 32; cb++) {
            uint32_t rg[32];
            TCGEN05_LD_32X32B_X32(rg, tbase + h * 256 + cb * 32);
            TCGEN05_WAIT_LD();
            #pragma unroll
            for (int q = 0; q < 8; q++) {
                const int c = cb * 32 + q * 4;
                float4 v;
                v.x = fmaf(__uint_as_float(rg[q * 4 + 0]), xsv * s_ws[c + 0], s_bi[c + 0]);
                v.y = fmaf(__uint_as_float(rg[q * 4 + 1]), xsv * s_ws[c + 1], s_bi[c + 1]);
                v.z = fmaf(__uint_as_float(rg[q * 4 + 2]), xsv * s_ws[c + 2], s_bi[c + 2]);
                v.w = fmaf(__uint_as_float(rg[q * 4 + 3]), xsv * s_ws[c + 3], s_bi[c + 3]);
                *reinterpret_cast<float4*>(orow + c) = v;
            }
        }
    }
    TCGEN05_FENCE_BEFORE();
    __syncthreads();
    if (wid == 0) {
        TCGEN05_RELINQUISH();
        TCGEN05_DEALLOC(tbase, 512);
    }

#else
    // =================== portable int8 mma.sync fallback ===================
    // 256x256 tile handled as two sequential 128-row halves.
    const int8_t* x8 = reinterpret_cast<const int8_t*>(g_xb);
    const int8_t* w8 = reinterpret_cast<const int8_t*>(g_wb);

    const int AST = 80, BST = 80;
    char* sA = smem;
    char* sB = smem + 128 * AST;
    const uint32_t sAu = smem_u32(sA);
    const uint32_t sBu = smem_u32(sB);
    const int warp_row = wid * 32;

    for (int mh = 0; mh < 2; mh++) {
        const int m0h = m0 + mh * 128;
        for (int nc = 0; nc < 4; nc++) {
            const int nb = n0 + nc * 64;
            int acc[2][8][4];
            #pragma unroll
            for (int a = 0; a < 2; a++)
                #pragma unroll
                for (int b = 0; b < 8; b++)
                    #pragma unroll
                    for (int c = 0; c < 4; c++) acc[a][b][c] = 0;

            for (int kt = 0; kt < 64; kt++) {
                const int k0 = kt * 64;
                __syncthreads();
                {
                    const uint4* src = reinterpret_cast<const uint4*>(
                        x8 + (size_t)(m0h + tid) * IN_F + k0);
                    uint4* dst = reinterpret_cast<uint4*>(sA + tid * AST);
                    #pragma unroll
                    for (int j = 0; j < 4; j++) dst[j] = src[j];
                }
                {
                    const int br = tid >> 1, hh = tid & 1;
                    const uint4* src = reinterpret_cast<const uint4*>(
                        w8 + (size_t)(nb + br) * IN_F + k0 + hh * 32);
                    uint4* dst = reinterpret_cast<uint4*>(sB + br * BST + hh * 32);
                    dst[0] = src[0]; dst[1] = src[1];
                }
                __syncthreads();

                #pragma unroll
                for (int s = 0; s < 2; s++) {
                    uint32_t afr[2][4];
                    #pragma unroll
                    for (int mt2 = 0; mt2 < 2; mt2++) {
                        uint32_t addr = sAu +
                            (uint32_t)(warp_row + mt2 * 16 + (lid & 15)) * AST +
                            s * 32 + ((lid >= 16) ? 16 : 0);
                        ldsm_x4(afr[mt2][0], afr[mt2][1], afr[mt2][2], afr[mt2][3], addr);
                    }
                    uint32_t bfr[4][4];
                    #pragma unroll
                    for (int p = 0; p < 4; p++) {
                        uint32_t addr = sBu +
                            (uint32_t)(p * 16 + (lid & 7) + ((lid >= 16) ? 8 : 0)) * BST +
                            s * 32 + ((lid & 8) ? 16 : 0);
                        ldsm_x4(bfr[p][0], bfr[p][1], bfr[p][2], bfr[p][3], addr);
                    }
                    #pragma unroll
                    for (int mt2 = 0; mt2 < 2; mt2++)
                        #pragma unroll
                        for (int nt2 = 0; nt2 < 8; nt2++) {
                            uint32_t bb[2];
                            bb[0] = bfr[nt2 >> 1][(nt2 & 1) ? 2 : 0];
                            bb[1] = bfr[nt2 >> 1][(nt2 & 1) ? 3 : 1];
                            imma16832(acc[mt2][nt2], afr[mt2], bb);
                        }
                }
            }
            #pragma unroll
            for (int mt2 = 0; mt2 < 2; mt2++) {
                const int r0_ = m0h + warp_row + mt2 * 16 + (lid >> 2);
                const float xs0 = xsc[r0_], xs1 = xsc[r0_ + 8];
                #pragma unroll
                for (int nt2 = 0; nt2 < 8; nt2++) {
                    const int c0 = nb + nt2 * 8 + (lid & 3) * 2;
                    const float w0 = wsc[c0], w1 = wsc[c0 + 1];
                    const float b0 = bias[c0], b1 = bias[c0 + 1];
                    float* o0 = out + (size_t)r0_ * OUT_F + c0;
                    float* o1 = out + (size_t)(r0_ + 8) * OUT_F + c0;
                    o0[0] = fmaf((float)acc[mt2][nt2][0], xs0 * w0, b0);
                    o0[1] = fmaf((float)acc[mt2][nt2][1], xs0 * w1, b1);
                    o1[0] = fmaf((float)acc[mt2][nt2][2], xs1 * w0, b0);
                    o1[1] = fmaf((float)acc[mt2][nt2][3], xs1 * w1, b1);
                }
            }
        }
    }
#endif
}

// ---------------------------------------------------------------------------
// Host launcher
// ---------------------------------------------------------------------------
typedef CUresult (*tmencode_fn_t)(
    CUtensorMap*, CUtensorMapDataType, cuuint32_t, void*,
    const cuuint64_t*, const cuuint64_t*, const cuuint32_t*, const cuuint32_t*,
    CUtensorMapInterleave, CUtensorMapSwizzle, CUtensorMapL2promotion,
    CUtensorMapFloatOOBfill);

extern "C" void kernel_launch(void* const* d_in, const int* in_sizes, int n_in,
                              void* d_out, int out_size) {
    const int*   x    = (const int*)d_in[0];
    const int*   w    = (const int*)d_in[1];
    const float* bias = (const float*)d_in[2];
    const float* xsc  = (const float*)d_in[3];
    const float* wsc  = (const float*)d_in[4];
    float* out = (float*)d_out;

    void* xb_ptr = nullptr;
    void* wb_ptr = nullptr;
    cudaGetSymbolAddress(&xb_ptr, g_xb);
    cudaGetSymbolAddress(&wb_ptr, g_wb);

    // Pre-pass: int32 -> (bf16 | int8), matching whichever GEMM variant loads.
    {
        int n4x = TOKENS * IN_F / 4;
        int n4w = OUT_F * IN_F / 4;
        cvt_kernel<<<(n4x + 255) / 256, 256>>>((const int4*)x, xb_ptr, n4x);
        cvt_kernel<<<(n4w + 255) / 256, 256>>>((const int4*)w, wb_ptr, n4w);
    }

    // TMA descriptors (bf16, SW64: 64B inner box rows; unused by fallback).
    tmencode_fn_t enc = nullptr;
    {
        void* fn = nullptr;
        cudaDriverEntryPointQueryResult qres;
#if CUDART_VERSION >= 12050
        cudaGetDriverEntryPointByVersion("cuTensorMapEncodeTiled", &fn, 12000,
                                         cudaEnableDefault, &qres);
#else
        cudaGetDriverEntryPoint("cuTensorMapEncodeTiled", &fn,
                                cudaEnableDefault, &qres);
#endif
        enc = (tmencode_fn_t)fn;
    }

    alignas(64) CUtensorMap tmA, tmB;
    if (enc) {
        {
            cuuint64_t dims[2] = {IN_F, TOKENS};
            cuuint64_t strd[1] = {IN_F * 2ull};
            cuuint32_t box[2]  = {KC, TILE_M};          // 32 bf16 = 64B inner, 256 rows
            cuuint32_t es[2]   = {1, 1};
            enc(&tmA, CU_TENSOR_MAP_DATA_TYPE_BFLOAT16, 2, xb_ptr, dims, strd, box, es,
                CU_TENSOR_MAP_INTERLEAVE_NONE, CU_TENSOR_MAP_SWIZZLE_64B,
                CU_TENSOR_MAP_L2_PROMOTION_L2_128B, CU_TENSOR_MAP_FLOAT_OOB_FILL_NONE);
        }
        {
            cuuint64_t dims[2] = {IN_F, OUT_F};
            cuuint64_t strd[1] = {IN_F * 2ull};
            cuuint32_t box[2]  = {KC, TILE_N};          // 64B inner, 256 rows
            cuuint32_t es[2]   = {1, 1};
            enc(&tmB, CU_TENSOR_MAP_DATA_TYPE_BFLOAT16, 2, wb_ptr, dims, strd, box, es,
                CU_TENSOR_MAP_INTERLEAVE_NONE, CU_TENSOR_MAP_SWIZZLE_64B,
                CU_TENSOR_MAP_L2_PROMOTION_L2_128B, CU_TENSOR_MAP_FLOAT_OOB_FILL_NONE);
        }
    }

    cudaFuncSetAttribute(q8gemm_kernel,
                         cudaFuncAttributeMaxDynamicSharedMemorySize, SMEM_TOTAL);

    const int grid = (TOKENS / TILE_M) * (OUT_F / TILE_N);  // 2048
    q8gemm_kernel<<<grid, GTHREADS, SMEM_TOTAL>>>(tmA, tmB, bias, xsc, wsc, out);
}